// round 2
// baseline (speedup 1.0000x reference)
#include <cuda_runtime.h>
#include <math.h>

#define NS   8
#define KK   3
#define C    512
#define CB   128
#define NB   8
#define HW   1024          // 32*32
#define HW4  256           // HW / 4
#define GH   16            // NS*ALPHA
#define EPS  1e-5f

// ---- scratch (tiny, static device globals — no allocation) ----
__device__ float g_theta[NB * C * NS];   // [nb][c][s]
__device__ float g_u    [NB * CB * NS];  // [nb][cb][s]

// ============================================================
// Kernel 1: theta = mean over H*W. 4 planes per block, 128 thr.
// 8 independent float4 LDGs per thread front-batched (MLP=8).
// ============================================================
__global__ __launch_bounds__(128) void k_theta(const float* __restrict__ x) {
    int pg = blockIdx.x * 4;          // first plane of this block's group
    int t  = threadIdx.x;
    const float4* xin = reinterpret_cast<const float4*>(x);
    float4 va[4], vb[4];
    #pragma unroll
    for (int i = 0; i < 4; i++) {
        size_t base = (size_t)(pg + i) * HW4;
        va[i] = xin[base + t];
        vb[i] = xin[base + t + 128];
    }
    float s[4];
    #pragma unroll
    for (int i = 0; i < 4; i++) {
        s[i] = va[i].x + va[i].y + va[i].z + va[i].w
             + vb[i].x + vb[i].y + vb[i].z + vb[i].w;
        #pragma unroll
        for (int o = 16; o > 0; o >>= 1)
            s[i] += __shfl_down_sync(0xffffffffu, s[i], o);
    }
    __shared__ float ws[4][4];
    int warp = t >> 5, lane = t & 31;
    if (lane == 0) {
        #pragma unroll
        for (int i = 0; i < 4; i++) ws[i][warp] = s[i];
    }
    __syncthreads();
    if (t < 4) {
        float tot = ws[t][0] + ws[t][1] + ws[t][2] + ws[t][3];
        int plane = pg + t;
        int n  = plane / C, c = plane % C;
        int nb = n / NS,    sg = n % NS;
        g_theta[(nb * C + c) * NS + sg] = tot * (1.0f / HW);
    }
}

// ============================================================
// Kernel 2: L-branch conv1: u[nb,cb,s] = relu(BN(sum_c sum_dk
// l_w1[cb,c,dk] * theta_pad[nb,c,s+dk-1])).
// 64 blocks = (nb=8) x (cb-group of 16), 8 warps, warp->2 cb rows.
// theta staged in smem stride-11 (conflict-free).
// ============================================================
__global__ __launch_bounds__(256) void k_lconv1(
    const float* __restrict__ lw1, const float* __restrict__ lg,
    const float* __restrict__ lb,  const float* __restrict__ lm,
    const float* __restrict__ lv) {
    __shared__ float thp[C * 11];
    int nb    = blockIdx.x >> 3;
    int group = blockIdx.x & 7;
    int tid = threadIdx.x;

    for (int idx = tid; idx < C * NS; idx += 256) {
        int c = idx >> 3, s = idx & 7;
        thp[c * 11 + s + 1] = g_theta[(nb * C + c) * NS + s];
    }
    for (int c = tid; c < C; c += 256) {
        thp[c * 11 + 0] = 0.f;
        thp[c * 11 + 9] = 0.f;
    }
    __syncthreads();

    int warp = tid >> 5, lane = tid & 31;
    #pragma unroll
    for (int i = 0; i < 2; i++) {
        int cb = group * 16 + warp * 2 + i;
        const float* wrow = lw1 + (size_t)cb * C * 3;
        float acc[NS] = {0.f,0.f,0.f,0.f,0.f,0.f,0.f,0.f};
        for (int c = lane; c < C; c += 32) {
            float w0 = wrow[c * 3 + 0];
            float w1 = wrow[c * 3 + 1];
            float w2 = wrow[c * 3 + 2];
            const float* tp = &thp[c * 11];
            #pragma unroll
            for (int s = 0; s < NS; s++)
                acc[s] += w0 * tp[s] + w1 * tp[s + 1] + w2 * tp[s + 2];
        }
        #pragma unroll
        for (int s = 0; s < NS; s++)
            #pragma unroll
            for (int o = 16; o > 0; o >>= 1)
                acc[s] += __shfl_down_sync(0xffffffffu, acc[s], o);
        if (lane == 0) {
            float sc = rsqrtf(lv[cb] + EPS) * lg[cb];
            float mu = lm[cb], be = lb[cb];
            #pragma unroll
            for (int s = 0; s < NS; s++) {
                float v = (acc[s] - mu) * sc + be;
                g_u[(nb * CB + cb) * NS + s] = fmaxf(v, 0.f);
            }
        }
    }
}

// ============================================================
// Kernel 3 (fused): per (nb,c) block —
//   prologue A: issue 8 x-plane float4 loads (DRAM latency cover)
//   prologue B: gate[s] (warp s: lconv2 dot over cb + sigmoid)
//               kcoef   (warp 0 lanes: G-branch MLP + softmax)
//   main: y = combined 3-tap temporal conv, x read exactly once.
// ============================================================
__global__ __launch_bounds__(256) void k_main(
    const float* __restrict__ x, float* __restrict__ y,
    const float* __restrict__ gw1, const float* __restrict__ gg,
    const float* __restrict__ gb,  const float* __restrict__ gm,
    const float* __restrict__ gv,  const float* __restrict__ gw2,
    const float* __restrict__ lw2) {
    __shared__ float w[NS][KK];
    __shared__ float sg[NS + 2];
    __shared__ float sk[KK];
    int nbc = blockIdx.x;             // nb*C + c
    int nb = nbc / C, c = nbc % C;
    int tid = threadIdx.x;
    int warp = tid >> 5, lane = tid & 31;

    // ---- issue x loads first (8 independent LDG.128) ----
    const float4* xin  = reinterpret_cast<const float4*>(x);
    float4*       yout = reinterpret_cast<float4*>(y);
    size_t base = ((size_t)(nb * NS) * C + c) * HW4 + tid;
    float4 xs[NS];
    #pragma unroll
    for (int s = 0; s < NS; s++) xs[s] = xin[base + (size_t)s * (C * HW4)];

    // ---- gate[s]: warp s computes sigmoid(sum_cb l_w2[c,cb]*u[nb,cb,s]) ----
    {
        int s = warp;                 // 8 warps == NS
        float acc = 0.f;
        #pragma unroll
        for (int i = 0; i < 4; i++) {
            int cb = lane + i * 32;
            acc += __ldg(lw2 + c * CB + cb) * g_u[(nb * CB + cb) * NS + s];
        }
        #pragma unroll
        for (int o = 16; o > 0; o >>= 1)
            acc += __shfl_down_sync(0xffffffffu, acc, o);
        if (lane == 0) sg[s + 1] = 1.f / (1.f + __expf(-acc));
    }
    if (tid == 0) { sg[0] = 0.f; sg[NS + 1] = 0.f; }

    // ---- kcoef: warp 0, lanes j<GH handle hidden unit j ----
    if (warp == 0) {
        float tj = 0.f;
        if (lane < GH) {
            #pragma unroll
            for (int s2 = 0; s2 < NS; s2++)
                tj += g_theta[(nb * C + c) * NS + s2] * __ldg(gw1 + lane * NS + s2);
            tj = (tj - __ldg(gm + lane)) * rsqrtf(__ldg(gv + lane) + EPS)
                 * __ldg(gg + lane) + __ldg(gb + lane);
            tj = fmaxf(tj, 0.f);
        }
        float l[KK];
        #pragma unroll
        for (int k = 0; k < KK; k++) {
            float v = (lane < GH) ? tj * __ldg(gw2 + k * GH + lane) : 0.f;
            #pragma unroll
            for (int o = 16; o > 0; o >>= 1)
                v += __shfl_down_sync(0xffffffffu, v, o);
            l[k] = v;
        }
        if (lane == 0) {
            float m  = fmaxf(l[0], fmaxf(l[1], l[2]));
            float e0 = __expf(l[0] - m), e1 = __expf(l[1] - m), e2 = __expf(l[2] - m);
            float inv = 1.f / (e0 + e1 + e2);
            sk[0] = e0 * inv; sk[1] = e1 * inv; sk[2] = e2 * inv;
        }
    }
    __syncthreads();

    if (tid < NS * KK) {
        int s = tid / KK, k = tid % KK;
        w[s][k] = sk[k] * sg[s + k];  // gate index s+k-1, +1 pad offset
    }
    __syncthreads();

    // ---- main: 3-tap temporal conv, all segments in registers ----
    #pragma unroll
    for (int s = 0; s < NS; s++) {
        float w0 = w[s][0], w1 = w[s][1], w2 = w[s][2];
        float4 r;
        r.x = w1 * xs[s].x; r.y = w1 * xs[s].y;
        r.z = w1 * xs[s].z; r.w = w1 * xs[s].w;
        if (s > 0) {
            r.x += w0 * xs[s-1].x; r.y += w0 * xs[s-1].y;
            r.z += w0 * xs[s-1].z; r.w += w0 * xs[s-1].w;
        }
        if (s < NS - 1) {
            r.x += w2 * xs[s+1].x; r.y += w2 * xs[s+1].y;
            r.z += w2 * xs[s+1].z; r.w += w2 * xs[s+1].w;
        }
        yout[base + (size_t)s * (C * HW4)] = r;
    }
}

// ============================================================
extern "C" void kernel_launch(void* const* d_in, const int* in_sizes, int n_in,
                              void* d_out, int out_size) {
    const float* x    = (const float*)d_in[0];
    const float* gw1  = (const float*)d_in[1];
    const float* ggam = (const float*)d_in[2];
    const float* gbet = (const float*)d_in[3];
    const float* gmea = (const float*)d_in[4];
    const float* gvar = (const float*)d_in[5];
    const float* gw2  = (const float*)d_in[6];
    const float* lw1  = (const float*)d_in[7];
    const float* lgam = (const float*)d_in[8];
    const float* lbet = (const float*)d_in[9];
    const float* lmea = (const float*)d_in[10];
    const float* lvar = (const float*)d_in[11];
    const float* lw2  = (const float*)d_in[12];
    float* y = (float*)d_out;

    k_theta <<<(NB * NS * C) / 4, 128>>>(x);
    k_lconv1<<<NB * 8, 256>>>(lw1, lgam, lbet, lmea, lvar);
    k_main  <<<NB * C, 256>>>(x, y, gw1, ggam, gbet, gmea, gvar, gw2, lw2);
}

// round 3
// speedup vs baseline: 1.0119x; 1.0119x over previous
#include <cuda_runtime.h>
#include <math.h>

#define NS   8
#define KK   3
#define C    512
#define CB   128
#define NB   8
#define HW   1024          // 32*32
#define HW4  256           // HW / 4
#define GH   16            // NS*ALPHA
#define EPS  1e-5f

// ---- scratch (tiny, static device globals — no allocation) ----
__device__ float g_theta[NB * C * NS];        // [nb][c][s]
__device__ float g_u    [NB * CB * NS];       // [nb][cb][s]
__device__ float g_w    [NB * C * NS * KK];   // [nb][c][s][k] combined weights

// ============================================================
// Kernel 1: theta = mean over H*W. 4 planes per block, 128 thr.
// ============================================================
__global__ __launch_bounds__(128) void k_theta(const float* __restrict__ x) {
    int pg = blockIdx.x * 4;
    int t  = threadIdx.x;
    const float4* xin = reinterpret_cast<const float4*>(x);
    float4 va[4], vb[4];
    #pragma unroll
    for (int i = 0; i < 4; i++) {
        size_t base = (size_t)(pg + i) * HW4;
        va[i] = xin[base + t];
        vb[i] = xin[base + t + 128];
    }
    float s[4];
    #pragma unroll
    for (int i = 0; i < 4; i++) {
        s[i] = va[i].x + va[i].y + va[i].z + va[i].w
             + vb[i].x + vb[i].y + vb[i].z + vb[i].w;
        #pragma unroll
        for (int o = 16; o > 0; o >>= 1)
            s[i] += __shfl_down_sync(0xffffffffu, s[i], o);
    }
    __shared__ float ws[4][4];
    int warp = t >> 5, lane = t & 31;
    if (lane == 0) {
        #pragma unroll
        for (int i = 0; i < 4; i++) ws[i][warp] = s[i];
    }
    __syncthreads();
    if (t < 4) {
        float tot = ws[t][0] + ws[t][1] + ws[t][2] + ws[t][3];
        int plane = pg + t;
        int n  = plane / C, c = plane % C;
        int nb = n / NS,    sg = n % NS;
        g_theta[(nb * C + c) * NS + sg] = tot * (1.0f / HW);
    }
}

// ============================================================
// Kernel 2: L-branch conv1 -> g_u. (unchanged)
// ============================================================
__global__ __launch_bounds__(256) void k_lconv1(
    const float* __restrict__ lw1, const float* __restrict__ lg,
    const float* __restrict__ lb,  const float* __restrict__ lm,
    const float* __restrict__ lv) {
    __shared__ float thp[C * 11];
    int nb    = blockIdx.x >> 3;
    int group = blockIdx.x & 7;
    int tid = threadIdx.x;

    for (int idx = tid; idx < C * NS; idx += 256) {
        int c = idx >> 3, s = idx & 7;
        thp[c * 11 + s + 1] = g_theta[(nb * C + c) * NS + s];
    }
    for (int c = tid; c < C; c += 256) {
        thp[c * 11 + 0] = 0.f;
        thp[c * 11 + 9] = 0.f;
    }
    __syncthreads();

    int warp = tid >> 5, lane = tid & 31;
    #pragma unroll
    for (int i = 0; i < 2; i++) {
        int cb = group * 16 + warp * 2 + i;
        const float* wrow = lw1 + (size_t)cb * C * 3;
        float acc[NS] = {0.f,0.f,0.f,0.f,0.f,0.f,0.f,0.f};
        for (int c = lane; c < C; c += 32) {
            float w0 = wrow[c * 3 + 0];
            float w1 = wrow[c * 3 + 1];
            float w2 = wrow[c * 3 + 2];
            const float* tp = &thp[c * 11];
            #pragma unroll
            for (int s = 0; s < NS; s++)
                acc[s] += w0 * tp[s] + w1 * tp[s + 1] + w2 * tp[s + 2];
        }
        #pragma unroll
        for (int s = 0; s < NS; s++)
            #pragma unroll
            for (int o = 16; o > 0; o >>= 1)
                acc[s] += __shfl_down_sync(0xffffffffu, acc[s], o);
        if (lane == 0) {
            float sc = rsqrtf(lv[cb] + EPS) * lg[cb];
            float mu = lm[cb], be = lb[cb];
            #pragma unroll
            for (int s = 0; s < NS; s++) {
                float v = (acc[s] - mu) * sc + be;
                g_u[(nb * CB + cb) * NS + s] = fmaxf(v, 0.f);
            }
        }
    }
}

// ============================================================
// Kernel 3: combined-weight precompute. One thread per (nb,c):
//   gate[s] = sigmoid(sum_cb lw2[c,cb] * u[nb,cb,s])  (u in smem)
//   kcoef   = softmax(MLP(theta_row))
//   g_w[nbc][s][k] = kcoef[k] * gate_pad[s+k-1]
// Grid: NB*4 blocks x 128 threads (block covers 128 c of one nb).
// ============================================================
__global__ __launch_bounds__(128) void k_wcomb(
    const float* __restrict__ gw1, const float* __restrict__ gg,
    const float* __restrict__ gb,  const float* __restrict__ gm,
    const float* __restrict__ gv,  const float* __restrict__ gw2,
    const float* __restrict__ lw2) {
    __shared__ float su[CB * NS];             // 4 KB, broadcast reads
    int nb  = blockIdx.x >> 2;
    int cg  = blockIdx.x & 3;
    int tid = threadIdx.x;

    const float* up = g_u + (size_t)nb * CB * NS;
    #pragma unroll
    for (int i = 0; i < (CB * NS) / 128; i++)
        su[tid + i * 128] = up[tid + i * 128];
    __syncthreads();

    int c = cg * 128 + tid;

    // gate accumulation: lw2 row contiguous per thread (float4)
    float acc[NS] = {0.f,0.f,0.f,0.f,0.f,0.f,0.f,0.f};
    const float4* wrow = reinterpret_cast<const float4*>(lw2 + (size_t)c * CB);
    #pragma unroll 8
    for (int q = 0; q < CB / 4; q++) {
        float4 wv = __ldg(wrow + q);
        const float* u0 = &su[(q * 4 + 0) * NS];
        #pragma unroll
        for (int s = 0; s < NS; s++)
            acc[s] += wv.x * u0[s]      + wv.y * u0[NS + s]
                    + wv.z * u0[2*NS+s] + wv.w * u0[3*NS+s];
    }
    float gp[NS + 2];
    gp[0] = 0.f; gp[NS + 1] = 0.f;
    #pragma unroll
    for (int s = 0; s < NS; s++)
        gp[s + 1] = 1.f / (1.f + __expf(-acc[s]));

    // kcoef MLP (weights broadcast across threads)
    const float* th = g_theta + (size_t)(nb * C + c) * NS;
    float t8[NS];
    #pragma unroll
    for (int s = 0; s < NS; s++) t8[s] = th[s];
    float l[KK] = {0.f, 0.f, 0.f};
    #pragma unroll
    for (int j = 0; j < GH; j++) {
        float t = 0.f;
        #pragma unroll
        for (int s = 0; s < NS; s++) t += t8[s] * __ldg(gw1 + j * NS + s);
        t = (t - __ldg(gm + j)) * rsqrtf(__ldg(gv + j) + EPS) * __ldg(gg + j) + __ldg(gb + j);
        t = fmaxf(t, 0.f);
        #pragma unroll
        for (int k = 0; k < KK; k++) l[k] += t * __ldg(gw2 + k * GH + j);
    }
    float m  = fmaxf(l[0], fmaxf(l[1], l[2]));
    float e0 = __expf(l[0] - m), e1 = __expf(l[1] - m), e2 = __expf(l[2] - m);
    float inv = 1.f / (e0 + e1 + e2);
    float sk[KK] = {e0 * inv, e1 * inv, e2 * inv};

    float* wout = g_w + (size_t)(nb * C + c) * NS * KK;
    #pragma unroll
    for (int s = 0; s < NS; s++)
        #pragma unroll
        for (int k = 0; k < KK; k++)
            wout[s * KK + k] = sk[k] * gp[s + k];
}

// ============================================================
// Kernel 4: pure streaming gated temporal conv.
// Block per (nb,c): 24-float smem weight fill, 8 LDG.128,
// 24 FMA4, 8 STG.128. Low regs -> high occupancy.
// ============================================================
__global__ __launch_bounds__(256) void k_main(
    const float* __restrict__ x, float* __restrict__ y) {
    __shared__ float w[NS * KK];
    int nbc = blockIdx.x;
    int tid = threadIdx.x;
    if (tid < NS * KK) w[tid] = g_w[(size_t)nbc * NS * KK + tid];

    int nb = nbc / C, c = nbc % C;
    const float4* xin  = reinterpret_cast<const float4*>(x);
    float4*       yout = reinterpret_cast<float4*>(y);
    size_t base = ((size_t)(nb * NS) * C + c) * HW4 + tid;

    float4 xs[NS];
    #pragma unroll
    for (int s = 0; s < NS; s++) xs[s] = xin[base + (size_t)s * (C * HW4)];
    __syncthreads();

    #pragma unroll
    for (int s = 0; s < NS; s++) {
        float w0 = w[s * KK + 0], w1 = w[s * KK + 1], w2 = w[s * KK + 2];
        float4 r;
        r.x = w1 * xs[s].x; r.y = w1 * xs[s].y;
        r.z = w1 * xs[s].z; r.w = w1 * xs[s].w;
        if (s > 0) {
            r.x += w0 * xs[s-1].x; r.y += w0 * xs[s-1].y;
            r.z += w0 * xs[s-1].z; r.w += w0 * xs[s-1].w;
        }
        if (s < NS - 1) {
            r.x += w2 * xs[s+1].x; r.y += w2 * xs[s+1].y;
            r.z += w2 * xs[s+1].z; r.w += w2 * xs[s+1].w;
        }
        yout[base + (size_t)s * (C * HW4)] = r;
    }
}

// ============================================================
extern "C" void kernel_launch(void* const* d_in, const int* in_sizes, int n_in,
                              void* d_out, int out_size) {
    const float* x    = (const float*)d_in[0];
    const float* gw1  = (const float*)d_in[1];
    const float* ggam = (const float*)d_in[2];
    const float* gbet = (const float*)d_in[3];
    const float* gmea = (const float*)d_in[4];
    const float* gvar = (const float*)d_in[5];
    const float* gw2  = (const float*)d_in[6];
    const float* lw1  = (const float*)d_in[7];
    const float* lgam = (const float*)d_in[8];
    const float* lbet = (const float*)d_in[9];
    const float* lmea = (const float*)d_in[10];
    const float* lvar = (const float*)d_in[11];
    const float* lw2  = (const float*)d_in[12];
    float* y = (float*)d_out;

    k_theta <<<(NB * NS * C) / 4, 128>>>(x);
    k_lconv1<<<NB * 8, 256>>>(lw1, lgam, lbet, lmea, lvar);
    k_wcomb <<<NB * 4, 128>>>(gw1, ggam, gbet, gmea, gvar, gw2, lw2);
    k_main  <<<NB * C, 256>>>(x, y);
}